// round 6
// baseline (speedup 1.0000x reference)
#include <cuda_runtime.h>
#include <cstdint>

#define NG   2048
#define MAXN 500000
#define BN_EPS 1e-5f

// ---------------- scratch (device globals; no allocation allowed) ----------------
__device__ __align__(16) float g_h[(size_t)MAXN * 128];   // h, then y0 in-place
__device__ __align__(16) float g_lam1[NG * 128];
__device__ __align__(16) float g_lam2[NG * 128];
__device__ __align__(16) float g_psum[NG * 128];
__device__ __align__(16) float g_psq[NG * 128];
__device__ __align__(16) float g_scale[128];
__device__ __align__(16) float g_shift[128];
__device__ int g_seg[NG + 1];

typedef unsigned long long ull;

// ---------------- packed f32x2 helpers ----------------
__device__ __forceinline__ ull pk2(float a, float b) {
    ull r;
    asm("mov.b64 %0, {%1, %2};" : "=l"(r) : "f"(a), "f"(b));
    return r;
}
__device__ __forceinline__ ull fma2(ull a, ull b, ull c) {
    ull d;
    asm("fma.rn.f32x2 %0, %1, %2, %3;" : "=l"(d) : "l"(a), "l"(b), "l"(c));
    return d;
}
__device__ __forceinline__ float2 upk2(ull v) {
    float2 f;
    asm("mov.b64 {%0, %1}, %2;" : "=f"(f.x), "=f"(f.y) : "l"(v));
    return f;
}

// ---------------- cp.async helpers ----------------
__device__ __forceinline__ uint32_t smaddr(const void* p) {
    return (uint32_t)__cvta_generic_to_shared(p);
}
__device__ __forceinline__ void cp16(uint32_t d, const void* s, int n) {
    asm volatile("cp.async.ca.shared.global [%0], [%1], 16, %2;\n" :: "r"(d), "l"(s), "r"(n));
}
__device__ __forceinline__ void cp4(uint32_t d, const void* s, int n) {
    asm volatile("cp.async.ca.shared.global [%0], [%1], 4, %2;\n" :: "r"(d), "l"(s), "r"(n));
}
#define CP_COMMIT() asm volatile("cp.async.commit_group;\n" ::: "memory")
#define CP_WAIT0()  asm volatile("cp.async.wait_group 0;\n" ::: "memory")

// ---------------- K0: segment bounds via binary search (batch sorted) ----------------
__global__ void k_bounds(const int* __restrict__ batch, int N) {
    int g = blockIdx.x * blockDim.x + threadIdx.x;
    if (g > NG) return;
    int lo = 0, hi = N;
    while (lo < hi) {
        int mid = (lo + hi) >> 1;
        if (batch[mid] < g) lo = mid + 1; else hi = mid;
    }
    g_seg[g] = lo;
}

// ---------------- K1: per-graph col-sums of x0 (144 cols) + lam1 = xm @ l1w^T ----------------
__global__ void k_lam1(const float* __restrict__ x, const float* __restrict__ pers0,
                       const float* __restrict__ l1w, int N) {
    __shared__ float s_sum[2][144];
    __shared__ float s_xm[144];
    int g  = blockIdx.x;
    int lo = g_seg[g], hi = g_seg[g + 1];
    int t  = threadIdx.x;
    int phase = t / 144, col = t - phase * 144;

    float acc = 0.f;
    if (col < 128) {
        const float* p = x + col;
        for (int r = lo + phase; r < hi; r += 2) acc += p[(size_t)r * 128];
    } else {
        int j = col - 128;
        int pp = j >> 1, c = j & 1;
        const float* p = pers0 + (size_t)pp * 2 * N + c;
        for (int r = lo + phase; r < hi; r += 2) acc += p[2 * (size_t)r];
    }
    s_sum[phase][col] = acc;
    __syncthreads();
    if (t < 144) {
        float cnt = (float)max(hi - lo, 1);
        s_xm[t] = (s_sum[0][t] + s_sum[1][t]) / cnt;
    }
    __syncthreads();
    if (t < 128) {
        const float* w = l1w + t * 144;
        float a = 0.f;
#pragma unroll 8
        for (int k = 0; k < 144; ++k) a += s_xm[k] * w[k];
        g_lam1[g * 128 + t] = a;
    }
}

// ---------------- K2: h = relu(x0 @ g1w^T + g1b - lam1[g]) + h col-sums + lam2 ----------------
// One block per graph, 256 threads, 8x8 micro-tile, pipelined operand loads.
__global__ __launch_bounds__(256, 1) void k_gemm1(
    const float* __restrict__ x, const float* __restrict__ pers0,
    const float* __restrict__ g1w, const float* __restrict__ g1b,
    const float* __restrict__ l2w, int N) {
    extern __shared__ float sm[];
    float* ws   = sm;                         // [144][132] transposed weights
    float* xs   = sm + 144 * 132;             // [144][132] k-major x0 tile
    float* land = sm + 2 * 144 * 132;         // [128][148] row-major landing
    const int SL = 148;

    int g   = blockIdx.x;
    int lo  = g_seg[g], hi = g_seg[g + 1];
    int tid = threadIdx.x;
    int tc  = tid & 15, tr = tid >> 4;   // cols 8*tc.., rows 8*tr..

    auto issue = [&](int r0, int rem) {
#pragma unroll
        for (int it = 0; it < 16; ++it) {
            int idx = tid + it * 256;
            int r = idx >> 5, k4 = idx & 31;
            int rg = r0 + min(r, rem - 1);
            int n  = (r < rem) ? 16 : 0;
            cp16(smaddr(land + r * SL + 4 * k4), x + (size_t)rg * 128 + 4 * k4, n);
        }
#pragma unroll
        for (int it = 0; it < 8; ++it) {
            int idx = tid + it * 256;
            int r = idx >> 4, q = idx & 15;
            int pp = q >> 1, c = q & 1;
            int rg = r0 + min(r, rem - 1);
            int n  = (r < rem) ? 4 : 0;
            cp4(smaddr(land + r * SL + 128 + q),
                pers0 + (size_t)pp * 2 * N + 2 * (size_t)rg + c, n);
        }
    };

    if (lo < hi) { issue(lo, min(128, hi - lo)); CP_COMMIT(); }

    // stage ws transposed, conflict-free lane map (lanes: 16 j x 2 k4)
    {
        const float4* w4 = (const float4*)g1w;
        for (int it = 0; it < 18; ++it) {
            int idx = tid + it * 256;            // [0, 128*36)
            int b = idx & 15, a = (idx >> 4) & 1, c = idx >> 5;  // c in [0,144)
            int j  = (c & 7) * 16 + b;
            int k4 = (c >> 3) * 2 + a;           // [0,36)
            float4 v = w4[j * 36 + k4];
            int k = 4 * k4;
            ws[(k + 0) * 132 + j] = v.x;
            ws[(k + 1) * 132 + j] = v.y;
            ws[(k + 2) * 132 + j] = v.z;
            ws[(k + 3) * 132 + j] = v.w;
        }
    }

    float bias[8];
#pragma unroll
    for (int c = 0; c < 8; ++c)
        bias[c] = g1b[8 * tc + c] - g_lam1[g * 128 + 8 * tc + c];

    float hs[8] = {0.f, 0.f, 0.f, 0.f, 0.f, 0.f, 0.f, 0.f};

    for (int r0 = lo; r0 < hi; r0 += 128) {
        int rem = min(128, hi - r0);
        CP_WAIT0();
        __syncthreads();

        // transpose land -> xs (conflict-free lane map)
#pragma unroll
        for (int it = 0; it < 18; ++it) {
            int idx = tid + it * 256;            // [0, 128*36)
            int b = idx & 15, a = (idx >> 4) & 1, c = idx >> 5;
            int r  = (c & 7) * 16 + b;
            int k4 = (c >> 3) * 2 + a;
            float4 v = *(const float4*)(land + r * SL + 4 * k4);
            int k = 4 * k4;
            xs[(k + 0) * 132 + r] = v.x;
            xs[(k + 1) * 132 + r] = v.y;
            xs[(k + 2) * 132 + r] = v.z;
            xs[(k + 3) * 132 + r] = v.w;
        }
        __syncthreads();

        int nr0 = r0 + 128;
        if (nr0 < hi) { issue(nr0, min(128, hi - nr0)); CP_COMMIT(); }

        ull acc[4][8];
#pragma unroll
        for (int p = 0; p < 4; ++p)
#pragma unroll
            for (int c = 0; c < 8; ++c) acc[p][c] = 0ull;

        const float* xbase = xs + 8 * tr;
        const float* wbase = ws + 8 * tc;
        ulonglong2 xa = *(const ulonglong2*)(xbase);
        ulonglong2 xb = *(const ulonglong2*)(xbase + 4);
        float4 wv0 = *(const float4*)(wbase);
        float4 wv1 = *(const float4*)(wbase + 4);

#pragma unroll 4
        for (int k = 0; k < 144; ++k) {
            int kn = min(k + 1, 143);
            const float* xk = xbase + kn * 132;
            const float* wk = wbase + kn * 132;
            ulonglong2 nxa = *(const ulonglong2*)(xk);
            ulonglong2 nxb = *(const ulonglong2*)(xk + 4);
            float4 nwv0 = *(const float4*)(wk);
            float4 nwv1 = *(const float4*)(wk + 4);

            ull wp0 = pk2(wv0.x, wv0.x), wp1 = pk2(wv0.y, wv0.y);
            ull wp2 = pk2(wv0.z, wv0.z), wp3 = pk2(wv0.w, wv0.w);
            ull wp4 = pk2(wv1.x, wv1.x), wp5 = pk2(wv1.y, wv1.y);
            ull wp6 = pk2(wv1.z, wv1.z), wp7 = pk2(wv1.w, wv1.w);

            acc[0][0] = fma2(xa.x, wp0, acc[0][0]);
            acc[0][1] = fma2(xa.x, wp1, acc[0][1]);
            acc[0][2] = fma2(xa.x, wp2, acc[0][2]);
            acc[0][3] = fma2(xa.x, wp3, acc[0][3]);
            acc[0][4] = fma2(xa.x, wp4, acc[0][4]);
            acc[0][5] = fma2(xa.x, wp5, acc[0][5]);
            acc[0][6] = fma2(xa.x, wp6, acc[0][6]);
            acc[0][7] = fma2(xa.x, wp7, acc[0][7]);
            acc[1][0] = fma2(xa.y, wp0, acc[1][0]);
            acc[1][1] = fma2(xa.y, wp1, acc[1][1]);
            acc[1][2] = fma2(xa.y, wp2, acc[1][2]);
            acc[1][3] = fma2(xa.y, wp3, acc[1][3]);
            acc[1][4] = fma2(xa.y, wp4, acc[1][4]);
            acc[1][5] = fma2(xa.y, wp5, acc[1][5]);
            acc[1][6] = fma2(xa.y, wp6, acc[1][6]);
            acc[1][7] = fma2(xa.y, wp7, acc[1][7]);
            acc[2][0] = fma2(xb.x, wp0, acc[2][0]);
            acc[2][1] = fma2(xb.x, wp1, acc[2][1]);
            acc[2][2] = fma2(xb.x, wp2, acc[2][2]);
            acc[2][3] = fma2(xb.x, wp3, acc[2][3]);
            acc[2][4] = fma2(xb.x, wp4, acc[2][4]);
            acc[2][5] = fma2(xb.x, wp5, acc[2][5]);
            acc[2][6] = fma2(xb.x, wp6, acc[2][6]);
            acc[2][7] = fma2(xb.x, wp7, acc[2][7]);
            acc[3][0] = fma2(xb.y, wp0, acc[3][0]);
            acc[3][1] = fma2(xb.y, wp1, acc[3][1]);
            acc[3][2] = fma2(xb.y, wp2, acc[3][2]);
            acc[3][3] = fma2(xb.y, wp3, acc[3][3]);
            acc[3][4] = fma2(xb.y, wp4, acc[3][4]);
            acc[3][5] = fma2(xb.y, wp5, acc[3][5]);
            acc[3][6] = fma2(xb.y, wp6, acc[3][6]);
            acc[3][7] = fma2(xb.y, wp7, acc[3][7]);

            xa = nxa; xb = nxb; wv0 = nwv0; wv1 = nwv1;
        }

        // epilogue: relu, store h, accumulate col sums (valid rows only)
#pragma unroll
        for (int p = 0; p < 4; ++p) {
            float2 v[8];
#pragma unroll
            for (int c = 0; c < 8; ++c) v[c] = upk2(acc[p][c]);
            int rl = tr * 8 + 2 * p;
            if (rl < rem) {
                float4 h0 = make_float4(fmaxf(v[0].x + bias[0], 0.f),
                                        fmaxf(v[1].x + bias[1], 0.f),
                                        fmaxf(v[2].x + bias[2], 0.f),
                                        fmaxf(v[3].x + bias[3], 0.f));
                float4 h1 = make_float4(fmaxf(v[4].x + bias[4], 0.f),
                                        fmaxf(v[5].x + bias[5], 0.f),
                                        fmaxf(v[6].x + bias[6], 0.f),
                                        fmaxf(v[7].x + bias[7], 0.f));
                float4* dst = (float4*)(g_h + (size_t)(r0 + rl) * 128);
                dst[2 * tc] = h0; dst[2 * tc + 1] = h1;
                hs[0] += h0.x; hs[1] += h0.y; hs[2] += h0.z; hs[3] += h0.w;
                hs[4] += h1.x; hs[5] += h1.y; hs[6] += h1.z; hs[7] += h1.w;
            }
            if (rl + 1 < rem) {
                float4 h0 = make_float4(fmaxf(v[0].y + bias[0], 0.f),
                                        fmaxf(v[1].y + bias[1], 0.f),
                                        fmaxf(v[2].y + bias[2], 0.f),
                                        fmaxf(v[3].y + bias[3], 0.f));
                float4 h1 = make_float4(fmaxf(v[4].y + bias[4], 0.f),
                                        fmaxf(v[5].y + bias[5], 0.f),
                                        fmaxf(v[6].y + bias[6], 0.f),
                                        fmaxf(v[7].y + bias[7], 0.f));
                float4* dst = (float4*)(g_h + (size_t)(r0 + rl + 1) * 128);
                dst[2 * tc] = h0; dst[2 * tc + 1] = h1;
                hs[0] += h0.x; hs[1] += h0.y; hs[2] += h0.z; hs[3] += h0.w;
                hs[4] += h1.x; hs[5] += h1.y; hs[6] += h1.z; hs[7] += h1.w;
            }
        }
    }

    // deterministic reduce of h col-sums, then lam2 = hm @ l2w^T (alias land)
    float* s_red = land;            // [16][128]
    float* s_hm  = land + 16 * 128; // [128]
    __syncthreads();
    {
        float4* dst = (float4*)(s_red + tr * 128 + 8 * tc);
        dst[0] = make_float4(hs[0], hs[1], hs[2], hs[3]);
        dst[1] = make_float4(hs[4], hs[5], hs[6], hs[7]);
    }
    __syncthreads();
    if (tid < 128) {
        float s = 0.f;
#pragma unroll
        for (int i = 0; i < 16; ++i) s += s_red[i * 128 + tid];
        float cnt = (float)max(hi - lo, 1);
        s_hm[tid] = s / cnt;
    }
    __syncthreads();
    if (tid < 128) {
        const float* w = l2w + tid * 128;
        float a = 0.f;
#pragma unroll 8
        for (int k = 0; k < 128; ++k) a += s_hm[k] * w[k];
        g_lam2[g * 128 + tid] = a;
    }
}

// ---------------- K4: y0 = h @ g2w^T + g2b - lam2[g]; in-place; BN partials ----------------
__global__ __launch_bounds__(256, 1) void k_gemm2(
    const float* __restrict__ g2w, const float* __restrict__ g2b, int N) {
    extern __shared__ float sm[];
    float* ws   = sm;                         // [128][132]
    float* xs   = sm + 128 * 132;             // [128][132]
    float* land = sm + 2 * 128 * 132;         // [128][132]
    const int SL = 132;

    int g   = blockIdx.x;
    int lo  = g_seg[g], hi = g_seg[g + 1];
    int tid = threadIdx.x;
    int tc  = tid & 15, tr = tid >> 4;

    auto issue = [&](int r0, int rem) {
#pragma unroll
        for (int it = 0; it < 16; ++it) {
            int idx = tid + it * 256;
            int r = idx >> 5, k4 = idx & 31;
            int rg = r0 + min(r, rem - 1);
            int n  = (r < rem) ? 16 : 0;
            cp16(smaddr(land + r * SL + 4 * k4), g_h + (size_t)rg * 128 + 4 * k4, n);
        }
    };

    if (lo < hi) { issue(lo, min(128, hi - lo)); CP_COMMIT(); }

    {
        const float4* w4 = (const float4*)g2w;
        for (int it = 0; it < 16; ++it) {
            int idx = tid + it * 256;            // [0, 128*32)
            int b = idx & 15, a = (idx >> 4) & 1, c = idx >> 5;  // c in [0,128)
            int j  = (c & 7) * 16 + b;
            int k4 = (c >> 3) * 2 + a;           // [0,32)
            float4 v = w4[j * 32 + k4];
            int k = 4 * k4;
            ws[(k + 0) * 132 + j] = v.x;
            ws[(k + 1) * 132 + j] = v.y;
            ws[(k + 2) * 132 + j] = v.z;
            ws[(k + 3) * 132 + j] = v.w;
        }
    }

    float bias[8];
#pragma unroll
    for (int c = 0; c < 8; ++c)
        bias[c] = g2b[8 * tc + c] - g_lam2[g * 128 + 8 * tc + c];

    float ssum[8] = {0.f, 0.f, 0.f, 0.f, 0.f, 0.f, 0.f, 0.f};
    float ssq[8]  = {0.f, 0.f, 0.f, 0.f, 0.f, 0.f, 0.f, 0.f};

    for (int r0 = lo; r0 < hi; r0 += 128) {
        int rem = min(128, hi - r0);
        CP_WAIT0();
        __syncthreads();

#pragma unroll
        for (int it = 0; it < 16; ++it) {
            int idx = tid + it * 256;
            int b = idx & 15, a = (idx >> 4) & 1, c = idx >> 5;
            int r  = (c & 7) * 16 + b;
            int k4 = (c >> 3) * 2 + a;
            float4 v = *(const float4*)(land + r * SL + 4 * k4);
            int k = 4 * k4;
            xs[(k + 0) * 132 + r] = v.x;
            xs[(k + 1) * 132 + r] = v.y;
            xs[(k + 2) * 132 + r] = v.z;
            xs[(k + 3) * 132 + r] = v.w;
        }
        __syncthreads();

        int nr0 = r0 + 128;
        if (nr0 < hi) { issue(nr0, min(128, hi - nr0)); CP_COMMIT(); }

        ull acc[4][8];
#pragma unroll
        for (int p = 0; p < 4; ++p)
#pragma unroll
            for (int c = 0; c < 8; ++c) acc[p][c] = 0ull;

        const float* xbase = xs + 8 * tr;
        const float* wbase = ws + 8 * tc;
        ulonglong2 xa = *(const ulonglong2*)(xbase);
        ulonglong2 xb = *(const ulonglong2*)(xbase + 4);
        float4 wv0 = *(const float4*)(wbase);
        float4 wv1 = *(const float4*)(wbase + 4);

#pragma unroll 4
        for (int k = 0; k < 128; ++k) {
            int kn = min(k + 1, 127);
            const float* xk = xbase + kn * 132;
            const float* wk = wbase + kn * 132;
            ulonglong2 nxa = *(const ulonglong2*)(xk);
            ulonglong2 nxb = *(const ulonglong2*)(xk + 4);
            float4 nwv0 = *(const float4*)(wk);
            float4 nwv1 = *(const float4*)(wk + 4);

            ull wp0 = pk2(wv0.x, wv0.x), wp1 = pk2(wv0.y, wv0.y);
            ull wp2 = pk2(wv0.z, wv0.z), wp3 = pk2(wv0.w, wv0.w);
            ull wp4 = pk2(wv1.x, wv1.x), wp5 = pk2(wv1.y, wv1.y);
            ull wp6 = pk2(wv1.z, wv1.z), wp7 = pk2(wv1.w, wv1.w);

            acc[0][0] = fma2(xa.x, wp0, acc[0][0]);
            acc[0][1] = fma2(xa.x, wp1, acc[0][1]);
            acc[0][2] = fma2(xa.x, wp2, acc[0][2]);
            acc[0][3] = fma2(xa.x, wp3, acc[0][3]);
            acc[0][4] = fma2(xa.x, wp4, acc[0][4]);
            acc[0][5] = fma2(xa.x, wp5, acc[0][5]);
            acc[0][6] = fma2(xa.x, wp6, acc[0][6]);
            acc[0][7] = fma2(xa.x, wp7, acc[0][7]);
            acc[1][0] = fma2(xa.y, wp0, acc[1][0]);
            acc[1][1] = fma2(xa.y, wp1, acc[1][1]);
            acc[1][2] = fma2(xa.y, wp2, acc[1][2]);
            acc[1][3] = fma2(xa.y, wp3, acc[1][3]);
            acc[1][4] = fma2(xa.y, wp4, acc[1][4]);
            acc[1][5] = fma2(xa.y, wp5, acc[1][5]);
            acc[1][6] = fma2(xa.y, wp6, acc[1][6]);
            acc[1][7] = fma2(xa.y, wp7, acc[1][7]);
            acc[2][0] = fma2(xb.x, wp0, acc[2][0]);
            acc[2][1] = fma2(xb.x, wp1, acc[2][1]);
            acc[2][2] = fma2(xb.x, wp2, acc[2][2]);
            acc[2][3] = fma2(xb.x, wp3, acc[2][3]);
            acc[2][4] = fma2(xb.x, wp4, acc[2][4]);
            acc[2][5] = fma2(xb.x, wp5, acc[2][5]);
            acc[2][6] = fma2(xb.x, wp6, acc[2][6]);
            acc[2][7] = fma2(xb.x, wp7, acc[2][7]);
            acc[3][0] = fma2(xb.y, wp0, acc[3][0]);
            acc[3][1] = fma2(xb.y, wp1, acc[3][1]);
            acc[3][2] = fma2(xb.y, wp2, acc[3][2]);
            acc[3][3] = fma2(xb.y, wp3, acc[3][3]);
            acc[3][4] = fma2(xb.y, wp4, acc[3][4]);
            acc[3][5] = fma2(xb.y, wp5, acc[3][5]);
            acc[3][6] = fma2(xb.y, wp6, acc[3][6]);
            acc[3][7] = fma2(xb.y, wp7, acc[3][7]);

            xa = nxa; xb = nxb; wv0 = nwv0; wv1 = nwv1;
        }

#pragma unroll
        for (int p = 0; p < 4; ++p) {
            float2 v[8];
#pragma unroll
            for (int c = 0; c < 8; ++c) v[c] = upk2(acc[p][c]);
            int rl = tr * 8 + 2 * p;
            if (rl < rem) {
                float4 y0 = make_float4(v[0].x + bias[0], v[1].x + bias[1],
                                        v[2].x + bias[2], v[3].x + bias[3]);
                float4 y1 = make_float4(v[4].x + bias[4], v[5].x + bias[5],
                                        v[6].x + bias[6], v[7].x + bias[7]);
                float4* dst = (float4*)(g_h + (size_t)(r0 + rl) * 128);
                dst[2 * tc] = y0; dst[2 * tc + 1] = y1;
                ssum[0] += y0.x; ssum[1] += y0.y; ssum[2] += y0.z; ssum[3] += y0.w;
                ssum[4] += y1.x; ssum[5] += y1.y; ssum[6] += y1.z; ssum[7] += y1.w;
                ssq[0] += y0.x * y0.x; ssq[1] += y0.y * y0.y;
                ssq[2] += y0.z * y0.z; ssq[3] += y0.w * y0.w;
                ssq[4] += y1.x * y1.x; ssq[5] += y1.y * y1.y;
                ssq[6] += y1.z * y1.z; ssq[7] += y1.w * y1.w;
            }
            if (rl + 1 < rem) {
                float4 y0 = make_float4(v[0].y + bias[0], v[1].y + bias[1],
                                        v[2].y + bias[2], v[3].y + bias[3]);
                float4 y1 = make_float4(v[4].y + bias[4], v[5].y + bias[5],
                                        v[6].y + bias[6], v[7].y + bias[7]);
                float4* dst = (float4*)(g_h + (size_t)(r0 + rl + 1) * 128);
                dst[2 * tc] = y0; dst[2 * tc + 1] = y1;
                ssum[0] += y0.x; ssum[1] += y0.y; ssum[2] += y0.z; ssum[3] += y0.w;
                ssum[4] += y1.x; ssum[5] += y1.y; ssum[6] += y1.z; ssum[7] += y1.w;
                ssq[0] += y0.x * y0.x; ssq[1] += y0.y * y0.y;
                ssq[2] += y0.z * y0.z; ssq[3] += y0.w * y0.w;
                ssq[4] += y1.x * y1.x; ssq[5] += y1.y * y1.y;
                ssq[6] += y1.z * y1.z; ssq[7] += y1.w * y1.w;
            }
        }
    }

    // deterministic per-graph BN partials (alias land)
    float* s_red = land;  // [16][128]
    __syncthreads();
    {
        float4* dst = (float4*)(s_red + tr * 128 + 8 * tc);
        dst[0] = make_float4(ssum[0], ssum[1], ssum[2], ssum[3]);
        dst[1] = make_float4(ssum[4], ssum[5], ssum[6], ssum[7]);
    }
    __syncthreads();
    float a = 0.f;
    if (tid < 128) {
#pragma unroll
        for (int i = 0; i < 16; ++i) a += s_red[i * 128 + tid];
    }
    __syncthreads();
    {
        float4* dst = (float4*)(s_red + tr * 128 + 8 * tc);
        dst[0] = make_float4(ssq[0], ssq[1], ssq[2], ssq[3]);
        dst[1] = make_float4(ssq[4], ssq[5], ssq[6], ssq[7]);
    }
    __syncthreads();
    if (tid < 128) {
        float b = 0.f;
#pragma unroll
        for (int i = 0; i < 16; ++i) b += s_red[i * 128 + tid];
        g_psum[g * 128 + tid] = a;
        g_psq[g * 128 + tid]  = b;
    }
}

// ---------------- K5: BN stats -> scale/shift ----------------
__global__ void k_stats(const float* __restrict__ bn_g, const float* __restrict__ bn_b, int N) {
    int t = threadIdx.x;  // 128
    float s = 0.f, q = 0.f;
    for (int g = 0; g < NG; ++g) {
        s += g_psum[g * 128 + t];
        q += g_psq[g * 128 + t];
    }
    float invN = 1.f / (float)N;
    float mu  = s * invN;
    float var = fmaxf(q * invN - mu * mu, 0.f);
    float sc  = rsqrtf(var + BN_EPS) * bn_g[t];
    g_scale[t] = sc;
    g_shift[t] = bn_b[t] - mu * sc;
}

// ---------------- K6: out = x + y0*scale + shift ----------------
__global__ void k_out(const float* __restrict__ x, float* __restrict__ out, int total4) {
    int i = blockIdx.x * blockDim.x + threadIdx.x;
    if (i >= total4) return;
    int j4 = i & 31;
    float4 sc = ((const float4*)g_scale)[j4];
    float4 sh = ((const float4*)g_shift)[j4];
    float4 xv = ((const float4*)x)[i];
    float4 yv = ((const float4*)g_h)[i];
    float4 o;
    o.x = xv.x + yv.x * sc.x + sh.x;
    o.y = xv.y + yv.y * sc.y + sh.y;
    o.z = xv.z + yv.z * sc.z + sh.z;
    o.w = xv.w + yv.w * sc.w + sh.w;
    ((float4*)out)[i] = o;
}

// ---------------- launch ----------------
extern "C" void kernel_launch(void* const* d_in, const int* in_sizes, int n_in,
                              void* d_out, int out_size) {
    const float* x     = (const float*)d_in[0];
    const int*   batch = (const int*)d_in[1];
    const float* pers0 = (const float*)d_in[2];
    const float* g1w   = (const float*)d_in[3];
    const float* g1b   = (const float*)d_in[4];
    const float* l1w   = (const float*)d_in[5];
    const float* g2w   = (const float*)d_in[6];
    const float* g2b   = (const float*)d_in[7];
    const float* l2w   = (const float*)d_in[8];
    const float* bng   = (const float*)d_in[9];
    const float* bnb   = (const float*)d_in[10];
    float* out = (float*)d_out;
    int N = in_sizes[0] / 128;

    const int smem1 = (2 * 144 * 132 + 128 * 148) * 4;  // 227,840 B
    const int smem2 = (3 * 128 * 132) * 4;              // 202,752 B
    cudaFuncSetAttribute(k_gemm1, cudaFuncAttributeMaxDynamicSharedMemorySize, smem1);
    cudaFuncSetAttribute(k_gemm2, cudaFuncAttributeMaxDynamicSharedMemorySize, smem2);

    k_bounds<<<(NG + 256) / 256, 256>>>(batch, N);
    k_lam1<<<NG, 288>>>(x, pers0, l1w, N);
    k_gemm1<<<NG, 256, smem1>>>(x, pers0, g1w, g1b, l2w, N);
    k_gemm2<<<NG, 256, smem2>>>(g2w, g2b, N);
    k_stats<<<1, 128>>>(bng, bnb, N);
    int total4 = N * 32;
    k_out<<<(total4 + 255) / 256, 256>>>(x, out, total4);
}

// round 9
// speedup vs baseline: 1.3010x; 1.3010x over previous
#include <cuda_runtime.h>
#include <cuda_bf16.h>
#include <cstdint>

#define NG   2048
#define MAXN 500000
#define BN_EPS 1e-5f

typedef unsigned long long ull;

// ---------------- scratch (device globals; no allocation allowed) ----------------
__device__ __align__(16) __nv_bfloat16 g_hhi[(size_t)MAXN * 128];
__device__ __align__(16) __nv_bfloat16 g_hlo[(size_t)MAXN * 128];
__device__ __align__(16) float g_y[(size_t)MAXN * 128];
__device__ __align__(16) float g_lam1[NG * 128];
__device__ __align__(16) float g_lam2[NG * 128];
__device__ __align__(16) float g_psum[NG * 128];
__device__ __align__(16) float g_psq[NG * 128];
__device__ __align__(16) float g_scale[128];
__device__ __align__(16) float g_shift[128];
__device__ int g_seg[NG + 1];

// ---------------- helpers ----------------
__device__ __forceinline__ uint32_t smaddr(const void* p) {
    return (uint32_t)__cvta_generic_to_shared(p);
}
__device__ __forceinline__ void cp16(uint32_t d, const void* s, int n) {
    asm volatile("cp.async.ca.shared.global [%0], [%1], 16, %2;\n" :: "r"(d), "l"(s), "r"(n));
}
#define CP_COMMIT() asm volatile("cp.async.commit_group;\n" ::: "memory")
#define CP_WAIT0()  asm volatile("cp.async.wait_group 0;\n" ::: "memory")

// bf16x2 mma (m16n8k16, sm_80+, compiles for plain sm_103)
__device__ __forceinline__ void mma_bf16(float* d, const uint32_t* a, const uint32_t* b) {
    asm volatile(
        "mma.sync.aligned.m16n8k16.row.col.f32.bf16.bf16.f32 "
        "{%0,%1,%2,%3}, {%4,%5,%6,%7}, {%8,%9}, {%0,%1,%2,%3};"
        : "+f"(d[0]), "+f"(d[1]), "+f"(d[2]), "+f"(d[3])
        : "r"(a[0]), "r"(a[1]), "r"(a[2]), "r"(a[3]), "r"(b[0]), "r"(b[1]));
}
__device__ __forceinline__ void ldsm4(uint32_t* r, uint32_t a) {
    asm volatile("ldmatrix.sync.aligned.m8n8.x4.shared.b16 {%0,%1,%2,%3}, [%4];"
        : "=r"(r[0]), "=r"(r[1]), "=r"(r[2]), "=r"(r[3]) : "r"(a));
}

// split fp32 pair -> packed bf16 hi / lo residual
__device__ __forceinline__ void bsplit2(float a, float b, uint32_t& hi, uint32_t& lo) {
    __nv_bfloat162 h = __floats2bfloat162_rn(a, b);
    hi = *reinterpret_cast<uint32_t*>(&h);
    float ra = a - __bfloat162float(h.x);
    float rb = b - __bfloat162float(h.y);
    __nv_bfloat162 l = __floats2bfloat162_rn(ra, rb);
    lo = *reinterpret_cast<uint32_t*>(&l);
}

#define ROWB 304            // bytes per operand row in smem (conflict-free for ldmatrix)
#define OFF_BH 512
#define OFF_BL (OFF_BH + 38912)
#define OFF_A  (OFF_BL + 38912)       // 2 bufs x (hi,lo) x 64*304
#define OFF_EPI (OFF_A + 77824)       // 4224 floats: red/epi/hm
#define SMEM_GEMM (OFF_EPI + 16896)   // 173056 B

// ---------------- K0: segment bounds (batch sorted) ----------------
__global__ void k_bounds(const int* __restrict__ batch, int N) {
    int g = blockIdx.x * blockDim.x + threadIdx.x;
    if (g > NG) return;
    int lo = 0, hi = N;
    while (lo < hi) {
        int mid = (lo + hi) >> 1;
        if (batch[mid] < g) lo = mid + 1; else hi = mid;
    }
    g_seg[g] = lo;
}

// ---------------- K1: per-graph col means of x0 + lam1 = xm @ l1w^T ----------------
__global__ void k_lam1(const float* __restrict__ x, const float* __restrict__ pers0,
                       const float* __restrict__ l1w, int N) {
    __shared__ float s_sum[2][144];
    __shared__ float s_xm[144];
    int g  = blockIdx.x;
    int lo = g_seg[g], hi = g_seg[g + 1];
    int t  = threadIdx.x;
    int phase = t / 144, col = t - phase * 144;

    float acc = 0.f;
    if (col < 128) {
        const float* p = x + col;
        for (int r = lo + phase; r < hi; r += 2) acc += p[(size_t)r * 128];
    } else {
        int j = col - 128;
        int pp = j >> 1, c = j & 1;
        const float* p = pers0 + (size_t)pp * 2 * N + c;
        for (int r = lo + phase; r < hi; r += 2) acc += p[2 * (size_t)r];
    }
    s_sum[phase][col] = acc;
    __syncthreads();
    if (t < 144) {
        float cnt = (float)max(hi - lo, 1);
        s_xm[t] = (s_sum[0][t] + s_sum[1][t]) / cnt;
    }
    __syncthreads();
    if (t < 128) {
        const float* w = l1w + t * 144;
        float a = 0.f;
#pragma unroll 8
        for (int k = 0; k < 144; ++k) a += s_xm[k] * w[k];
        g_lam1[g * 128 + t] = a;
    }
}

// =============== K2: mma.sync GEMM1: h = relu(x0 @ g1w^T + g1b - lam1[g]) ===============
// 8 warps: wm=wid&3 (16 rows each), wn=wid>>2 (64 cols each). K=144 = 9 k16-steps.
// Split bf16: D += Ahi*Bhi + Ahi*Blo + Alo*Bhi.
__global__ __launch_bounds__(256, 1) void k_gemm1(
    const float* __restrict__ x, const float* __restrict__ pers0,
    const float* __restrict__ g1w, const float* __restrict__ g1b,
    const float* __restrict__ l2w, int N) {
    extern __shared__ char sm[];
    uint32_t su = smaddr(sm);
    float* sbias = (float*)sm;
    int g  = blockIdx.x;
    int lo = g_seg[g], hi = g_seg[g + 1];
    int tid = threadIdx.x;
    int wid = tid >> 5, l = tid & 31;
    int wm = wid & 3, wn = wid >> 2;
    int seg = l >> 3, l7 = l & 7, gg = l >> 2, tg = l & 3;

    // stage B = g1w (already [out][k] = col-major KxN) as bf16 hi/lo, row stride 304B
    for (int it = 0; it < 18; ++it) {
        int idx = tid + it * 256;            // [0, 128*36)
        int jr = idx / 36, k4 = idx - jr * 36;
        float4 v = ((const float4*)g1w)[idx];
        uint32_t h01, l01, h23, l23;
        bsplit2(v.x, v.y, h01, l01);
        bsplit2(v.z, v.w, h23, l23);
        int off = jr * ROWB + k4 * 8;
        *(uint2*)(sm + OFF_BH + off) = make_uint2(h01, h23);
        *(uint2*)(sm + OFF_BL + off) = make_uint2(l01, l23);
    }
    if (tid < 128) sbias[tid] = g1b[tid] - g_lam1[g * 128 + tid];

    // register prefetch of one 64-row x0 tile (row = tid>>2, k-quarter = tid&3)
    float4 xv[8]; float2 pv[2];
    int prow = tid >> 2, pkq = tid & 3;
    auto loadRegs = [&](int r0i, int rem) {
        int rg = r0i + min(prow, rem - 1);
        const float4* xs = (const float4*)(x + (size_t)rg * 128) + pkq * 8;
#pragma unroll
        for (int i = 0; i < 8; ++i) xv[i] = xs[i];
        int p0 = pkq * 2;
        pv[0] = *(const float2*)(pers0 + (size_t)p0 * 2 * N + 2 * (size_t)rg);
        pv[1] = *(const float2*)(pers0 + (size_t)(p0 + 1) * 2 * N + 2 * (size_t)rg);
    };
    auto stsRegs = [&](int buf) {
        char* bh = sm + OFF_A + buf * 38912 + prow * ROWB;
        char* bl = bh + 19456;
#pragma unroll
        for (int i = 0; i < 8; ++i) {
            uint32_t h01, l01, h23, l23;
            bsplit2(xv[i].x, xv[i].y, h01, l01);
            bsplit2(xv[i].z, xv[i].w, h23, l23);
            *(uint2*)(bh + pkq * 64 + i * 8) = make_uint2(h01, h23);
            *(uint2*)(bl + pkq * 64 + i * 8) = make_uint2(l01, l23);
        }
        uint32_t h01, l01, h23, l23;
        bsplit2(pv[0].x, pv[0].y, h01, l01);
        bsplit2(pv[1].x, pv[1].y, h23, l23);
        *(uint2*)(bh + 256 + pkq * 8) = make_uint2(h01, h23);
        *(uint2*)(bl + 256 + pkq * 8) = make_uint2(l01, l23);
    };

    float hs[16];
#pragma unroll
    for (int i = 0; i < 16; ++i) hs[i] = 0.f;

    // ldmatrix per-lane addresses
    uint32_t a_off  = su + OFF_A  + (uint32_t)((wm * 16 + (seg & 1) * 8 + l7) * ROWB + (seg >> 1) * 16);
    uint32_t b_off  = su + OFF_BH + (uint32_t)((wn * 64 + (seg >> 1) * 8 + l7) * ROWB + (seg & 1) * 16);

    if (lo < hi) { loadRegs(lo, min(64, hi - lo)); stsRegs(0); }
    __syncthreads();

    int t = 0;
    for (int r0 = lo; r0 < hi; r0 += 64, ++t) {
        int rem = min(64, hi - r0);
        int buf = t & 1;
        int nr0 = r0 + 64;
        bool havnext = nr0 < hi;
        if (havnext) loadRegs(nr0, min(64, hi - nr0));   // LDG in flight over compute

        float D[8][4];
#pragma unroll
        for (int i = 0; i < 8; ++i)
#pragma unroll
            for (int q = 0; q < 4; ++q) D[i][q] = 0.f;

        uint32_t abase = a_off + buf * 38912;
#pragma unroll
        for (int ks = 0; ks < 9; ++ks) {
            uint32_t ah[4], al[4];
            ldsm4(ah, abase + ks * 32);
            ldsm4(al, abase + 19456 + ks * 32);
#pragma unroll
            for (int nt = 0; nt < 4; ++nt) {
                uint32_t bb = b_off + nt * (16 * ROWB) + ks * 32;
                uint32_t bhf[4], blf[4];
                ldsm4(bhf, bb);
                ldsm4(blf, bb + 38912);
                mma_bf16(D[2 * nt],     ah, bhf);
                mma_bf16(D[2 * nt + 1], ah, bhf + 2);
                mma_bf16(D[2 * nt],     ah, blf);
                mma_bf16(D[2 * nt + 1], ah, blf + 2);
                mma_bf16(D[2 * nt],     al, bhf);
                mma_bf16(D[2 * nt + 1], al, bhf + 2);
            }
        }
        if (havnext) stsRegs(buf ^ 1);

        // epilogue: 2 half-tiles of 32 rows through smem (coalesced stores + col sums)
        float* epi = (float*)(sm + OFF_EPI);
#pragma unroll
        for (int p = 0; p < 2; ++p) {
            __syncthreads();
            if ((wm >> 1) == p) {
                int er = (wm & 1) * 16 + gg;
#pragma unroll
                for (int nt = 0; nt < 8; ++nt) {
                    int c = wn * 64 + nt * 8 + 2 * tg;
                    *(float2*)(epi + er * 132 + c)       = make_float2(D[nt][0], D[nt][1]);
                    *(float2*)(epi + (er + 8) * 132 + c) = make_float2(D[nt][2], D[nt][3]);
                }
            }
            __syncthreads();
            int r = tid >> 3, c0 = (tid & 7) * 16;
            int grow = r0 + p * 32 + r;
            if (grow < hi) {
                float v[16];
#pragma unroll
                for (int q = 0; q < 4; ++q)
                    *(float4*)(v + 4 * q) = *(const float4*)(epi + r * 132 + c0 + 4 * q);
                uint32_t hh[8], ll[8];
#pragma unroll
                for (int i = 0; i < 16; i += 2) {
                    float va = fmaxf(v[i]     + sbias[c0 + i],     0.f);
                    float vb = fmaxf(v[i + 1] + sbias[c0 + i + 1], 0.f);
                    hs[i] += va; hs[i + 1] += vb;
                    bsplit2(va, vb, hh[i >> 1], ll[i >> 1]);
                }
                size_t off = (size_t)grow * 128 + c0;
                *(uint4*)(g_hhi + off)     = make_uint4(hh[0], hh[1], hh[2], hh[3]);
                *(uint4*)(g_hhi + off + 8) = make_uint4(hh[4], hh[5], hh[6], hh[7]);
                *(uint4*)(g_hlo + off)     = make_uint4(ll[0], ll[1], ll[2], ll[3]);
                *(uint4*)(g_hlo + off + 8) = make_uint4(ll[4], ll[5], ll[6], ll[7]);
            }
        }
        __syncthreads();
    }

    // deterministic col-sum reduce -> hm -> lam2 = hm @ l2w^T
    float* red = (float*)(sm + OFF_EPI);
    __syncthreads();
#pragma unroll
    for (int i = 0; i < 16; ++i) red[tid * 16 + i] = hs[i];
    __syncthreads();
    if (tid < 128) {
        int o = tid >> 4, i = tid & 15;
        float s = 0.f;
        for (int ss = 0; ss < 32; ++ss) s += red[(ss * 8 + o) * 16 + i];
        float cnt = (float)max(hi - lo, 1);
        red[4096 + o * 16 + i] = s / cnt;
    }
    __syncthreads();
    if (tid < 128) {
        const float* w = l2w + tid * 128;
        const float* hm = red + 4096;
        float a = 0.f;
#pragma unroll 8
        for (int k = 0; k < 128; ++k) a += hm[k] * w[k];
        g_lam2[g * 128 + tid] = a;
    }
}

// =============== K4: mma.sync GEMM2: y0 = h @ g2w^T + g2b - lam2[g]; BN partials ===============
__global__ __launch_bounds__(256, 1) void k_gemm2(
    const float* __restrict__ g2w, const float* __restrict__ g2b, int N) {
    extern __shared__ char sm[];
    uint32_t su = smaddr(sm);
    float* sbias = (float*)sm;
    int g  = blockIdx.x;
    int lo = g_seg[g], hi = g_seg[g + 1];
    int tid = threadIdx.x;
    int wid = tid >> 5, l = tid & 31;
    int wm = wid & 3, wn = wid >> 2;
    int seg = l >> 3, l7 = l & 7, gg = l >> 2, tg = l & 3;

    // stage B = g2w bf16 hi/lo (K=128 -> 32 float4 per row)
    for (int it = 0; it < 16; ++it) {
        int idx = tid + it * 256;            // [0, 128*32)
        int jr = idx >> 5, k4 = idx & 31;
        float4 v = ((const float4*)g2w)[idx];
        uint32_t h01, l01, h23, l23;
        bsplit2(v.x, v.y, h01, l01);
        bsplit2(v.z, v.w, h23, l23);
        int off = jr * ROWB + k4 * 8;
        *(uint2*)(sm + OFF_BH + off) = make_uint2(h01, h23);
        *(uint2*)(sm + OFF_BL + off) = make_uint2(l01, l23);
    }
    if (tid < 128) sbias[tid] = g2b[tid] - g_lam2[g * 128 + tid];

    // A staging via cp.async from pre-split h arrays
    auto stageA = [&](int r0i, int rem, int buf) {
#pragma unroll
        for (int hl = 0; hl < 2; ++hl) {
            const __nv_bfloat16* src = hl ? g_hlo : g_hhi;
            uint32_t base = su + OFF_A + buf * 38912 + hl * 19456;
#pragma unroll
            for (int it = 0; it < 4; ++it) {
                int idx = tid + it * 256;        // [0, 64*16)
                int r = idx >> 4, u = idx & 15;
                int rc = (r < rem) ? r : 0;
                cp16(base + r * ROWB + u * 16,
                     src + (size_t)(r0i + rc) * 128 + u * 8, (r < rem) ? 16 : 0);
            }
        }
    };

    float ssum[16], ssq[16];
#pragma unroll
    for (int i = 0; i < 16; ++i) { ssum[i] = 0.f; ssq[i] = 0.f; }

    uint32_t a_off = su + OFF_A  + (uint32_t)((wm * 16 + (seg & 1) * 8 + l7) * ROWB + (seg >> 1) * 16);
    uint32_t b_off = su + OFF_BH + (uint32_t)((wn * 64 + (seg >> 1) * 8 + l7) * ROWB + (seg & 1) * 16);

    if (lo < hi) { stageA(lo, min(64, hi - lo), 0); CP_COMMIT(); CP_WAIT0(); }
    __syncthreads();

    int t = 0;
    for (int r0 = lo; r0 < hi; r0 += 64, ++t) {
        int rem = min(64, hi - r0);
        int buf = t & 1;
        int nr0 = r0 + 64;
        bool havnext = nr0 < hi;
        if (havnext) { stageA(nr0, min(64, hi - nr0), buf ^ 1); CP_COMMIT(); }

        float D[8][4];
#pragma unroll
        for (int i = 0; i < 8; ++i)
#pragma unroll
            for (int q = 0; q < 4; ++q) D[i][q] = 0.f;

        uint32_t abase = a_off + buf * 38912;
#pragma unroll
        for (int ks = 0; ks < 8; ++ks) {
            uint32_t ah[4], al[4];
            ldsm4(ah, abase + ks * 32);
            ldsm4(al, abase + 19456 + ks * 32);
#pragma unroll
            for (int nt = 0; nt < 4; ++nt) {
                uint32_t bb = b_off + nt * (16 * ROWB) + ks * 32;
                uint32_t bhf[4], blf[4];
                ldsm4(bhf, bb);
                ldsm4(blf, bb + 38912);
                mma_bf16(D[2 * nt],     ah, bhf);
                mma_bf16(D[2 * nt + 1], ah, bhf + 2);
                mma_bf16(D[2 * nt],     ah, blf);
                mma_bf16(D[2 * nt + 1], ah, blf + 2);
                mma_bf16(D[2 * nt],     al, bhf);
                mma_bf16(D[2 * nt + 1], al, bhf + 2);
            }
        }

        float* epi = (float*)(sm + OFF_EPI);
#pragma unroll
        for (int p = 0; p < 2; ++p) {
            __syncthreads();
            if ((wm >> 1) == p) {
                int er = (wm & 1) * 16 + gg;
#pragma unroll
                for (int nt = 0; nt < 8; ++nt) {
                    int c = wn * 64 + nt * 8 + 2 * tg;
                    *(float2*)(epi + er * 132 + c)       = make_float2(D[nt][0], D[nt][1]);
                    *(float2*)(epi + (er + 8) * 132 + c) = make_float2(D[nt][2], D[nt][3]);
                }
            }
            __syncthreads();
            int r = tid >> 3, c0 = (tid & 7) * 16;
            int grow = r0 + p * 32 + r;
            if (grow < hi) {
                float v[16];
#pragma unroll
                for (int q = 0; q < 4; ++q)
                    *(float4*)(v + 4 * q) = *(const float4*)(epi + r * 132 + c0 + 4 * q);
#pragma unroll
                for (int i = 0; i < 16; ++i) {
                    float vv = v[i] + sbias[c0 + i];
                    v[i] = vv;
                    ssum[i] += vv;
                    ssq[i]  += vv * vv;
                }
                float* dst = g_y + (size_t)grow * 128 + c0;
#pragma unroll
                for (int q = 0; q < 4; ++q) *(float4*)(dst + 4 * q) = *(float4*)(v + 4 * q);
            }
        }
        if (havnext) CP_WAIT0();
        __syncthreads();
    }

    // deterministic BN partials
    float* red = (float*)(sm + OFF_EPI);
    __syncthreads();
#pragma unroll
    for (int i = 0; i < 16; ++i) red[tid * 16 + i] = ssum[i];
    __syncthreads();
    if (tid < 128) {
        int o = tid >> 4, i = tid & 15;
        float s = 0.f;
        for (int ss = 0; ss < 32; ++ss) s += red[(ss * 8 + o) * 16 + i];
        g_psum[g * 128 + o * 16 + i] = s;
    }
    __syncthreads();
#pragma unroll
    for (int i = 0; i < 16; ++i) red[tid * 16 + i] = ssq[i];
    __syncthreads();
    if (tid < 128) {
        int o = tid >> 4, i = tid & 15;
        float s = 0.f;
        for (int ss = 0; ss < 32; ++ss) s += red[(ss * 8 + o) * 16 + i];
        g_psq[g * 128 + o * 16 + i] = s;
    }
}

// ---------------- K5: BN stats -> scale/shift ----------------
__global__ void k_stats(const float* __restrict__ bn_g, const float* __restrict__ bn_b, int N) {
    int t = threadIdx.x;  // 128
    float s = 0.f, q = 0.f;
    for (int g = 0; g < NG; ++g) {
        s += g_psum[g * 128 + t];
        q += g_psq[g * 128 + t];
    }
    float invN = 1.f / (float)N;
    float mu  = s * invN;
    float var = fmaxf(q * invN - mu * mu, 0.f);
    float sc  = rsqrtf(var + BN_EPS) * bn_g[t];
    g_scale[t] = sc;
    g_shift[t] = bn_b[t] - mu * sc;
}

// ---------------- K6: out = x + y0*scale + shift ----------------
__global__ void k_out(const float* __restrict__ x, float* __restrict__ out, int total4) {
    int i = blockIdx.x * blockDim.x + threadIdx.x;
    if (i >= total4) return;
    int j4 = i & 31;
    float4 sc = ((const float4*)g_scale)[j4];
    float4 sh = ((const float4*)g_shift)[j4];
    float4 xv = ((const float4*)x)[i];
    float4 yv = ((const float4*)g_y)[i];
    float4 o;
    o.x = xv.x + yv.x * sc.x + sh.x;
    o.y = xv.y + yv.y * sc.y + sh.y;
    o.z = xv.z + yv.z * sc.z + sh.z;
    o.w = xv.w + yv.w * sc.w + sh.w;
    ((float4*)out)[i] = o;
}

// ---------------- launch ----------------
extern "C" void kernel_launch(void* const* d_in, const int* in_sizes, int n_in,
                              void* d_out, int out_size) {
    const float* x     = (const float*)d_in[0];
    const int*   batch = (const int*)d_in[1];
    const float* pers0 = (const float*)d_in[2];
    const float* g1w   = (const float*)d_in[3];
    const float* g1b   = (const float*)d_in[4];
    const float* l1w   = (const float*)d_in[5];
    const float* g2w   = (const float*)d_in[6];
    const float* g2b   = (const float*)d_in[7];
    const float* l2w   = (const float*)d_in[8];
    const float* bng   = (const float*)d_in[9];
    const float* bnb   = (const float*)d_in[10];
    float* out = (float*)d_out;
    int N = in_sizes[0] / 128;

    cudaFuncSetAttribute(k_gemm1, cudaFuncAttributeMaxDynamicSharedMemorySize, SMEM_GEMM);
    cudaFuncSetAttribute(k_gemm2, cudaFuncAttributeMaxDynamicSharedMemorySize, SMEM_GEMM);

    k_bounds<<<(NG + 256) / 256, 256>>>(batch, N);
    k_lam1<<<NG, 288>>>(x, pers0, l1w, N);
    k_gemm1<<<NG, 256, SMEM_GEMM>>>(x, pers0, g1w, g1b, l2w, N);
    k_gemm2<<<NG, 256, SMEM_GEMM>>>(g2w, g2b, N);
    k_stats<<<1, 128>>>(bng, bnb, N);
    int total4 = N * 32;
    k_out<<<(total4 + 255) / 256, 256>>>(x, out, total4);
}